// round 1
// baseline (speedup 1.0000x reference)
#include <cuda_runtime.h>
#include <math.h>

// Problem constants
#define T_TOK 8192
#define NE 8
#define TOPK 2
#define HID 1024
#define INTER 4096
#define CAP 2560          // ceil(8192*2*1.25/8) = 2560

// ---------------- device scratch (no allocations allowed) ----------------
__device__ float g_disp[NE * CAP * HID];                 // dispatched tokens  (84 MB)
__device__ float g_inter[(size_t)NE * CAP * INTER];     // SiLU(gate)*up      (335 MB)
__device__ float g_eout[NE * CAP * HID];                 // expert outputs     (84 MB)
__device__ int   g_dest[T_TOK * TOPK];                   // slot or -1
__device__ int   g_counts[NE];                           // tokens routed per expert

// ---------------- routing: ballot-scan positions per expert ----------------
// 1 block, 256 threads = 8 warps; warp w owns expert w.
__global__ void routing_kernel(const int* __restrict__ eidx) {
    int e    = threadIdx.x >> 5;
    int lane = threadIdx.x & 31;
    int running = 0;
    for (int base = 0; base < T_TOK; base += 32) {
        int t  = base + lane;
        int i0 = eidx[2 * t];
        int i1 = eidx[2 * t + 1];
        bool h0 = (i0 == e);
        bool h1 = (i1 == e);
        unsigned b = __ballot_sync(0xFFFFFFFFu, h0 || h1);
        int pos = running + __popc(b & ((1u << lane) - 1u));
        if (h0) g_dest[2 * t]     = (pos < CAP) ? e * CAP + pos : -1;
        if (h1) g_dest[2 * t + 1] = (pos < CAP) ? e * CAP + pos : -1;
        running += __popc(b);
    }
    if (lane == 0) g_counts[e] = running;
}

// ---------------- dispatch: scatter token rows into expert buffers ----------------
// grid = T_TOK*TOPK blocks, 128 threads
__global__ void dispatch_kernel(const float* __restrict__ x) {
    int slot = g_dest[blockIdx.x];
    if (slot < 0) return;
    int t = blockIdx.x >> 1;
    const float4* src = (const float4*)(x + (size_t)t * HID);
    float4* dst = (float4*)(g_disp + (size_t)slot * HID);
#pragma unroll
    for (int i = threadIdx.x; i < HID / 4; i += 128) dst[i] = src[i];
}

// ---------------- GEMM1 + GLU: inter = silu(X*Wg) * (X*Wu) ----------------
// grid = (INTER/64, CAP/128, NE), 256 threads. Tile: 128 rows x 64 inter-cols.
// Per thread: 8x4 gate accum + 8x4 up accum.
__global__ __launch_bounds__(256) void gemm1_glu_kernel(const float* __restrict__ W) {
    const int z    = blockIdx.z;
    const int used = min(g_counts[z], CAP);
    const int row0 = blockIdx.y * 128;
    if (row0 >= used) return;

    const float* A  = g_disp + (size_t)z * CAP * HID;
    const float* Bg = W + (size_t)z * HID * (2 * INTER) + blockIdx.x * 64;
    const float* Bu = Bg + INTER;

    __shared__ float As[16][132];
    __shared__ float Bgs[16][68];
    __shared__ float Bus[16][68];

    float accg[8][4] = {};
    float accu[8][4] = {};

    const int tid = threadIdx.x;
    const int tx  = tid & 15;        // N dir (x4)
    const int ty  = tid >> 4;        // M dir (x8)
    const int ar  = tid >> 2;        // A row within tile: 0..63 (+64)
    const int ac  = (tid & 3) * 4;   // A col within K-tile
    const int br  = tid >> 4;        // B K-row 0..15
    const int bc  = (tid & 15) * 4;  // B col 0..60

    for (int kt = 0; kt < HID; kt += 16) {
#pragma unroll
        for (int h = 0; h < 2; h++) {
            int r = ar + h * 64;
            float4 v = *(const float4*)(A + (size_t)(row0 + r) * HID + kt + ac);
            As[ac + 0][r] = v.x; As[ac + 1][r] = v.y;
            As[ac + 2][r] = v.z; As[ac + 3][r] = v.w;
        }
        *(float4*)&Bgs[br][bc] = *(const float4*)(Bg + (size_t)(kt + br) * (2 * INTER) + bc);
        *(float4*)&Bus[br][bc] = *(const float4*)(Bu + (size_t)(kt + br) * (2 * INTER) + bc);
        __syncthreads();

#pragma unroll
        for (int k = 0; k < 16; k++) {
            float a[8], bg[4], bu[4];
#pragma unroll
            for (int i = 0; i < 8; i++) a[i] = As[k][ty * 8 + i];
#pragma unroll
            for (int j = 0; j < 4; j++) { bg[j] = Bgs[k][tx * 4 + j]; bu[j] = Bus[k][tx * 4 + j]; }
#pragma unroll
            for (int i = 0; i < 8; i++)
#pragma unroll
                for (int j = 0; j < 4; j++) {
                    accg[i][j] += a[i] * bg[j];
                    accu[i][j] += a[i] * bu[j];
                }
        }
        __syncthreads();
    }

    float* O = g_inter + (size_t)z * CAP * INTER + (size_t)blockIdx.x * 64;
#pragma unroll
    for (int i = 0; i < 8; i++) {
        int r = row0 + ty * 8 + i;
        float vv[4];
#pragma unroll
        for (int j = 0; j < 4; j++) {
            float g = accg[i][j];
            float s = g / (1.0f + __expf(-g));
            vv[j] = s * accu[i][j];
        }
        *(float4*)(O + (size_t)r * INTER + tx * 4) = make_float4(vv[0], vv[1], vv[2], vv[3]);
    }
}

// ---------------- GEMM2: eout = inter * Wd ----------------
// grid = (HID/128, CAP/128, NE), 256 threads, 128x128 tile, 8x8 per thread.
__global__ __launch_bounds__(256) void gemm2_kernel(const float* __restrict__ Wd) {
    const int z    = blockIdx.z;
    const int used = min(g_counts[z], CAP);
    const int row0 = blockIdx.y * 128;
    if (row0 >= used) return;

    const float* A = g_inter + (size_t)z * CAP * INTER;
    const float* B = Wd + (size_t)z * INTER * HID + blockIdx.x * 128;

    __shared__ float As[16][132];
    __shared__ float Bs[16][132];

    float acc[8][8] = {};

    const int tid = threadIdx.x;
    const int tx  = tid & 15;
    const int ty  = tid >> 4;
    const int ar  = tid >> 2;
    const int ac  = (tid & 3) * 4;
    const int br  = tid >> 5;        // 0..7 (+8)
    const int bc  = (tid & 31) * 4;  // 0..124

    for (int kt = 0; kt < INTER; kt += 16) {
#pragma unroll
        for (int h = 0; h < 2; h++) {
            int r = ar + h * 64;
            float4 v = *(const float4*)(A + (size_t)(row0 + r) * INTER + kt + ac);
            As[ac + 0][r] = v.x; As[ac + 1][r] = v.y;
            As[ac + 2][r] = v.z; As[ac + 3][r] = v.w;
        }
#pragma unroll
        for (int h = 0; h < 2; h++) {
            int r = br + h * 8;
            *(float4*)&Bs[r][bc] = *(const float4*)(B + (size_t)(kt + r) * HID + bc);
        }
        __syncthreads();

#pragma unroll
        for (int k = 0; k < 16; k++) {
            float a[8], b[8];
#pragma unroll
            for (int i = 0; i < 8; i++) a[i] = As[k][ty * 8 + i];
#pragma unroll
            for (int j = 0; j < 8; j++) b[j] = Bs[k][tx * 8 + j];
#pragma unroll
            for (int i = 0; i < 8; i++)
#pragma unroll
                for (int j = 0; j < 8; j++) acc[i][j] += a[i] * b[j];
        }
        __syncthreads();
    }

    float* O = g_eout + (size_t)z * CAP * HID + (size_t)blockIdx.x * 128;
#pragma unroll
    for (int i = 0; i < 8; i++) {
        int r = row0 + ty * 8 + i;
        *(float4*)(O + (size_t)r * HID + tx * 8)     = make_float4(acc[i][0], acc[i][1], acc[i][2], acc[i][3]);
        *(float4*)(O + (size_t)r * HID + tx * 8 + 4) = make_float4(acc[i][4], acc[i][5], acc[i][6], acc[i][7]);
    }
}

// ---------------- combine: weighted gather back to tokens ----------------
// grid = T_TOK blocks, 256 threads
__global__ void combine_kernel(const float* __restrict__ aff,
                               const int* __restrict__ eidx,
                               float* __restrict__ out) {
    int t  = blockIdx.x;
    int d0 = g_dest[2 * t];
    int d1 = g_dest[2 * t + 1];
    float a0 = aff[t * NE + eidx[2 * t]];
    float a1 = aff[t * NE + eidx[2 * t + 1]];
    float s  = a0 + a1;
    float w0 = (d0 >= 0) ? a0 / s : 0.0f;
    float w1 = (d1 >= 0) ? a1 / s : 0.0f;

    const float4* p0 = (d0 >= 0) ? (const float4*)(g_eout + (size_t)d0 * HID) : (const float4*)g_eout;
    const float4* p1 = (d1 >= 0) ? (const float4*)(g_eout + (size_t)d1 * HID) : (const float4*)g_eout;

    int i = threadIdx.x;           // HID/4 = 256 float4 per row, 256 threads
    float4 v0 = p0[i];
    float4 v1 = p1[i];
    float4 r;
    r.x = w0 * v0.x + w1 * v1.x;
    r.y = w0 * v0.y + w1 * v1.y;
    r.z = w0 * v0.z + w1 * v1.z;
    r.w = w0 * v0.w + w1 * v1.w;
    ((float4*)out)[(size_t)t * (HID / 4) + i] = r;
}

// ---------------- launcher ----------------
extern "C" void kernel_launch(void* const* d_in, const int* in_sizes, int n_in,
                              void* d_out, int out_size) {
    const float* hidden = (const float*)d_in[0];   // (S,B,H) = (T, H)
    const float* aff    = (const float*)d_in[1];   // (T, E)
    const int*   eidx   = (const int*)d_in[2];     // (T, K)
    const float* w_gu   = (const float*)d_in[3];   // (E, H, 2I)
    const float* w_dn   = (const float*)d_in[4];   // (E, I, H)
    float* out = (float*)d_out;

    routing_kernel<<<1, 256>>>(eidx);
    dispatch_kernel<<<T_TOK * TOPK, 128>>>(hidden);

    dim3 g1(INTER / 64, CAP / 128, NE);
    gemm1_glu_kernel<<<g1, 256>>>(w_gu);

    dim3 g2(HID / 128, CAP / 128, NE);
    gemm2_kernel<<<g2, 256>>>(w_dn);

    combine_kernel<<<T_TOK, 256>>>(aff, eidx, out);
}

// round 4
// speedup vs baseline: 1.9350x; 1.9350x over previous
#include <cuda_runtime.h>
#include <cuda_bf16.h>
#include <cstdint>
#include <math.h>

#define T_TOK 8192
#define NE 8
#define TOPK 2
#define HID 1024
#define INTER 4096
#define CAP 2560

// ---------------- device scratch ----------------
__device__ __nv_bfloat16 g_ahi[(size_t)NE * CAP * HID];
__device__ __nv_bfloat16 g_alo[(size_t)NE * CAP * HID];
__device__ __nv_bfloat16 g_w1hi[(size_t)NE * 2 * INTER * HID];  // transposed (E, 2I, H)
__device__ __nv_bfloat16 g_w1lo[(size_t)NE * 2 * INTER * HID];
__device__ __nv_bfloat16 g_w2hi[(size_t)NE * HID * INTER];      // transposed (E, H, I)
__device__ __nv_bfloat16 g_w2lo[(size_t)NE * HID * INTER];
__device__ __nv_bfloat16 g_ihi[(size_t)NE * CAP * INTER];
__device__ __nv_bfloat16 g_ilo[(size_t)NE * CAP * INTER];
__device__ float g_eout[(size_t)NE * CAP * HID];
__device__ int   g_dest[T_TOK * TOPK];
__device__ int   g_counts[NE];

// ---------------- PTX helpers (generic sm_80+ only) ----------------
__device__ __forceinline__ uint32_t smem_u32(const void* p) {
    uint32_t a;
    asm("{ .reg .u64 t; cvta.to.shared.u64 t, %1; cvt.u32.u64 %0, t; }" : "=r"(a) : "l"(p));
    return a;
}
__device__ __forceinline__ void cp16(uint32_t d, const void* s) {
    asm volatile("cp.async.cg.shared.global [%0], [%1], 16;" :: "r"(d), "l"(s));
}
#define CP_COMMIT() asm volatile("cp.async.commit_group;" ::: "memory")
#define CP_WAIT(n)  asm volatile("cp.async.wait_group %0;" :: "n"(n) : "memory")

__device__ __forceinline__ void ldsm4(uint32_t* r, uint32_t addr) {
    asm volatile("ldmatrix.sync.aligned.m8n8.x4.shared.b16 {%0,%1,%2,%3}, [%4];"
                 : "=r"(r[0]), "=r"(r[1]), "=r"(r[2]), "=r"(r[3]) : "r"(addr));
}
__device__ __forceinline__ void mma16816(float* c, const uint32_t* a, const uint32_t* b) {
    asm volatile("mma.sync.aligned.m16n8k16.row.col.f32.bf16.bf16.f32 "
                 "{%0,%1,%2,%3}, {%4,%5,%6,%7}, {%8,%9}, {%0,%1,%2,%3};"
                 : "+f"(c[0]), "+f"(c[1]), "+f"(c[2]), "+f"(c[3])
                 : "r"(a[0]), "r"(a[1]), "r"(a[2]), "r"(a[3]), "r"(b[0]), "r"(b[1]));
}
__device__ __forceinline__ uint32_t pack_bf16(float lo, float hi) {
    __nv_bfloat162 v = __floats2bfloat162_rn(lo, hi);
    return *(uint32_t*)&v;
}

// ---------------- routing ----------------
__global__ void routing_kernel(const int* __restrict__ eidx) {
    int e = threadIdx.x >> 5, lane = threadIdx.x & 31;
    int running = 0;
    for (int base = 0; base < T_TOK; base += 32) {
        int t = base + lane;
        bool h0 = (eidx[2 * t] == e);
        bool h1 = (eidx[2 * t + 1] == e);
        unsigned b = __ballot_sync(0xFFFFFFFFu, h0 || h1);
        int pos = running + __popc(b & ((1u << lane) - 1u));
        if (h0) g_dest[2 * t]     = (pos < CAP) ? e * CAP + pos : -1;
        if (h1) g_dest[2 * t + 1] = (pos < CAP) ? e * CAP + pos : -1;
        running += __popc(b);
    }
    if (lane == 0) g_counts[e] = running;
}

// ---------------- dispatch + bf16 split ----------------
__global__ void dispatch_split_kernel(const float* __restrict__ x) {
    int slot = g_dest[blockIdx.x];
    if (slot < 0) return;
    int t = blockIdx.x >> 1;
    int i = threadIdx.x;
    const float4* src = (const float4*)(x + (size_t)t * HID);
    float4 v0 = src[i * 2], v1 = src[i * 2 + 1];
    float vv[8] = {v0.x, v0.y, v0.z, v0.w, v1.x, v1.y, v1.z, v1.w};
    union { __nv_bfloat16 b[8]; uint4 u; } H, L;
#pragma unroll
    for (int k = 0; k < 8; k++) {
        __nv_bfloat16 hb = __float2bfloat16(vv[k]);
        H.b[k] = hb;
        L.b[k] = __float2bfloat16(vv[k] - __bfloat162float(hb));
    }
    *(uint4*)(g_ahi + (size_t)slot * HID + i * 8) = H.u;
    *(uint4*)(g_alo + (size_t)slot * HID + i * 8) = L.u;
}

// ---------------- weight split + transpose ----------------
__global__ void split_w1_kernel(const float* __restrict__ W) {
    __shared__ float tile[32][33];
    int z = blockIdx.z, jb = blockIdx.x * 32, hb = blockIdx.y * 32;
    int tx = threadIdx.x, ty = threadIdx.y;
    const float* src = W + (size_t)z * HID * (2 * INTER);
#pragma unroll
    for (int k = 0; k < 4; k++) {
        tile[ty + k * 8][tx] = src[(size_t)(hb + ty + k * 8) * (2 * INTER) + jb + tx];
    }
    __syncthreads();
    size_t base = (size_t)z * 2 * INTER * HID;
#pragma unroll
    for (int k = 0; k < 4; k++) {
        float v = tile[tx][ty + k * 8];
        __nv_bfloat16 hb16 = __float2bfloat16(v);
        size_t o = base + (size_t)(jb + ty + k * 8) * HID + hb + tx;
        g_w1hi[o] = hb16;
        g_w1lo[o] = __float2bfloat16(v - __bfloat162float(hb16));
    }
}
__global__ void split_w2_kernel(const float* __restrict__ W) {
    __shared__ float tile[32][33];
    int z = blockIdx.z, ib = blockIdx.x * 32, hb = blockIdx.y * 32;
    int tx = threadIdx.x, ty = threadIdx.y;
    const float* src = W + (size_t)z * INTER * HID;
#pragma unroll
    for (int k = 0; k < 4; k++) {
        tile[ty + k * 8][tx] = src[(size_t)(ib + ty + k * 8) * HID + hb + tx];
    }
    __syncthreads();
    size_t base = (size_t)z * HID * INTER;
#pragma unroll
    for (int k = 0; k < 4; k++) {
        float v = tile[tx][ty + k * 8];
        __nv_bfloat16 hb16 = __float2bfloat16(v);
        size_t o = base + (size_t)(hb + ty + k * 8) * INTER + ib + tx;
        g_w2hi[o] = hb16;
        g_w2lo[o] = __float2bfloat16(v - __bfloat162float(hb16));
    }
}

// ---------------- split-bf16 mma.sync GEMM ----------------
// Block tile: M=128 (slots) x N=128 tile cols, K chunk 32, 3-stage cp.async.
// 8 warps = 4(M) x 2(N). Warp covers 32 M-rows and tile cols
// [g*32, g*32+32) ∪ [64+g*32, 64+g*32+32).
// GLU: tile cols 0..63 = gate j (jb0..+63), 64..127 = up j  -> same-thread SiLU.
// Non-GLU: tile cols = output h cols directly.
static constexpr int TILE_B  = 128 * 80;        // one operand tile (80B pitch)
static constexpr int STAGE_B = 4 * TILE_B;      // Ahi, Alo, Bhi, Blo
static constexpr int STAGES  = 3;
static constexpr int SMEM_BYTES = STAGES * STAGE_B;   // 122880

template <int KTOT, bool GLU>
__global__ __launch_bounds__(256) void gemm_split_kernel() {
    extern __shared__ char smem[];
    const uint32_t sbase = smem_u32(smem);
    const int tid  = threadIdx.x;
    const int z    = blockIdx.z;
    const int used = min(g_counts[z], CAP);
    const int row0 = blockIdx.y * 128;
    if (row0 >= used) return;

    const __nv_bfloat16* Ahi = GLU ? g_ahi : g_ihi;
    const __nv_bfloat16* Alo = GLU ? g_alo : g_ilo;
    const __nv_bfloat16* Bhi = GLU ? g_w1hi : g_w2hi;
    const __nv_bfloat16* Blo = GLU ? g_w1lo : g_w2lo;
    const int pitch = GLU ? HID : INTER;     // same pitch for A and B here
    const size_t arow0 = (size_t)z * CAP + row0;
    const int jb0 = GLU ? blockIdx.x * 64 : blockIdx.x * 128;

    const int warp = tid >> 5, lane = tid & 31;
    const int wm = warp >> 1, g = warp & 1;
    const int q = lane >> 3, r8 = lane & 7;

    // lane-local ldmatrix offsets (within a tile, before row/kstep bases)
    const uint32_t aoff = (uint32_t)(((q & 1) * 8 + r8) * 80 + (q >> 1) * 16);
    const uint32_t boff = (uint32_t)(((q >> 1) * 8 + r8) * 80 + (q & 1) * 16);

    float acc[2][8][4];
#pragma unroll
    for (int a = 0; a < 2; a++)
#pragma unroll
        for (int b = 0; b < 8; b++)
#pragma unroll
            for (int c = 0; c < 4; c++) acc[a][b][c] = 0.0f;

    constexpr int NCH = KTOT / 32;

    // B-tile global row for a tile row index (0..127)
    auto browG = [&](int row) -> size_t {
        if (GLU) {
            return (size_t)z * (2 * INTER) +
                   (row < 64 ? (size_t)(jb0 + row) : (size_t)(INTER + jb0 + row - 64));
        }
        return (size_t)z * HID + jb0 + row;
    };

    auto load_chunk = [&](int stage, int kt) {
        uint32_t sb = sbase + stage * STAGE_B;
#pragma unroll
        for (int t = 0; t < 8; t++) {
            int idx = tid + t * 256;          // 0..2047
            int tile = idx >> 9;              // 0 Ahi, 1 Alo, 2 Bhi, 3 Blo
            int within = idx & 511;
            int row = within >> 2;
            int seg = within & 3;
            uint32_t dst = sb + tile * TILE_B + row * 80 + seg * 16;
            const __nv_bfloat16* src;
            if (tile < 2) {
                const __nv_bfloat16* base = (tile == 0) ? Ahi : Alo;
                src = base + (arow0 + row) * (size_t)pitch + kt + seg * 8;
            } else {
                const __nv_bfloat16* base = (tile == 2) ? Bhi : Blo;
                src = base + browG(row) * (size_t)pitch + kt + seg * 8;
            }
            cp16(dst, src);
        }
        CP_COMMIT();
    };

    // prologue
    load_chunk(0, 0);
    load_chunk(1, 32);
    load_chunk(2, 64);

    for (int i = 0; i < NCH; i++) {
        CP_WAIT(2);
        __syncthreads();
        uint32_t sb = sbase + (i % 3) * STAGE_B;

#pragma unroll
        for (int ks = 0; ks < 2; ks++) {
            uint32_t ah[2][4], al[2][4];
#pragma unroll
            for (int mt = 0; mt < 2; mt++) {
                uint32_t ra = (uint32_t)((wm * 32 + mt * 16) * 80 + ks * 32) + aoff;
                ldsm4(ah[mt], sb + 0 * TILE_B + ra);
                ldsm4(al[mt], sb + 1 * TILE_B + ra);
            }
            uint32_t bh[4][4], bl[4][4];
#pragma unroll
            for (int p = 0; p < 4; p++) {
                int n0 = (p < 2) ? (g * 32 + p * 16) : (64 + g * 32 + (p - 2) * 16);
                uint32_t rb = (uint32_t)(n0 * 80 + ks * 32) + boff;
                ldsm4(bh[p], sb + 2 * TILE_B + rb);
                ldsm4(bl[p], sb + 3 * TILE_B + rb);
            }
#pragma unroll
            for (int mt = 0; mt < 2; mt++) {
#pragma unroll
                for (int nt = 0; nt < 8; nt++) {
                    const int p = nt >> 1, h = (nt & 1) * 2;
                    mma16816(acc[mt][nt], ah[mt], &bh[p][h]);   // hi*hi
                    mma16816(acc[mt][nt], ah[mt], &bl[p][h]);   // hi*lo
                    mma16816(acc[mt][nt], al[mt], &bh[p][h]);   // lo*hi
                }
            }
        }
        __syncthreads();
        if (i + 3 < NCH) load_chunk((i + 3) % 3, (i + 3) * 32);
    }

    // ---------------- epilogue ----------------
    const int rbase = row0 + wm * 32 + (lane >> 2);
    const int cofs = (lane & 3) * 2;

    if (GLU) {
#pragma unroll
        for (int mt = 0; mt < 2; mt++) {
#pragma unroll
            for (int nt = 0; nt < 4; nt++) {
                float* ga = acc[mt][nt];
                float* ua = acc[mt][nt + 4];
                int j = jb0 + g * 32 + nt * 8 + cofs;
#pragma unroll
                for (int hrow = 0; hrow < 2; hrow++) {
                    int rr = rbase + mt * 16 + hrow * 8;
                    float g0 = ga[hrow * 2], g1 = ga[hrow * 2 + 1];
                    float u0 = ua[hrow * 2], u1 = ua[hrow * 2 + 1];
                    float y0 = g0 / (1.0f + __expf(-g0)) * u0;
                    float y1 = g1 / (1.0f + __expf(-g1)) * u1;
                    __nv_bfloat16 h0 = __float2bfloat16(y0);
                    __nv_bfloat16 h1 = __float2bfloat16(y1);
                    float l0 = y0 - __bfloat162float(h0);
                    float l1 = y1 - __bfloat162float(h1);
                    size_t off = ((size_t)z * CAP + rr) * INTER + j;
                    uint32_t hp; { __nv_bfloat162 v; v.x = h0; v.y = h1; hp = *(uint32_t*)&v; }
                    *(uint32_t*)(g_ihi + off) = hp;
                    *(uint32_t*)(g_ilo + off) = pack_bf16(l0, l1);
                }
            }
        }
    } else {
#pragma unroll
        for (int mt = 0; mt < 2; mt++) {
#pragma unroll
            for (int nt = 0; nt < 8; nt++) {
                int c = (nt < 4) ? (g * 32 + nt * 8) : (64 + g * 32 + (nt - 4) * 8);
                int hcol = jb0 + c + cofs;
#pragma unroll
                for (int hrow = 0; hrow < 2; hrow++) {
                    int rr = rbase + mt * 16 + hrow * 8;
                    size_t off = ((size_t)z * CAP + rr) * HID + hcol;
                    *(float2*)(g_eout + off) =
                        make_float2(acc[mt][nt][hrow * 2], acc[mt][nt][hrow * 2 + 1]);
                }
            }
        }
    }
}

// ---------------- combine ----------------
__global__ void combine_kernel(const float* __restrict__ aff,
                               const int* __restrict__ eidx,
                               float* __restrict__ out) {
    int t  = blockIdx.x;
    int d0 = g_dest[2 * t];
    int d1 = g_dest[2 * t + 1];
    float a0 = aff[t * NE + eidx[2 * t]];
    float a1 = aff[t * NE + eidx[2 * t + 1]];
    float s  = a0 + a1;
    float w0 = (d0 >= 0) ? a0 / s : 0.0f;
    float w1 = (d1 >= 0) ? a1 / s : 0.0f;
    const float4* p0 = (d0 >= 0) ? (const float4*)(g_eout + (size_t)d0 * HID) : (const float4*)g_eout;
    const float4* p1 = (d1 >= 0) ? (const float4*)(g_eout + (size_t)d1 * HID) : (const float4*)g_eout;
    int i = threadIdx.x;
    float4 v0 = p0[i], v1 = p1[i], r;
    r.x = w0 * v0.x + w1 * v1.x;
    r.y = w0 * v0.y + w1 * v1.y;
    r.z = w0 * v0.z + w1 * v1.z;
    r.w = w0 * v0.w + w1 * v1.w;
    ((float4*)out)[(size_t)t * (HID / 4) + i] = r;
}

// ---------------- launcher ----------------
extern "C" void kernel_launch(void* const* d_in, const int* in_sizes, int n_in,
                              void* d_out, int out_size) {
    const float* hidden = (const float*)d_in[0];
    const float* aff    = (const float*)d_in[1];
    const int*   eidx   = (const int*)d_in[2];
    const float* w_gu   = (const float*)d_in[3];
    const float* w_dn   = (const float*)d_in[4];
    float* out = (float*)d_out;

    cudaFuncSetAttribute(gemm_split_kernel<HID, true>,
                         cudaFuncAttributeMaxDynamicSharedMemorySize, SMEM_BYTES);
    cudaFuncSetAttribute(gemm_split_kernel<INTER, false>,
                         cudaFuncAttributeMaxDynamicSharedMemorySize, SMEM_BYTES);

    routing_kernel<<<1, 256>>>(eidx);
    dispatch_split_kernel<<<T_TOK * TOPK, 128>>>(hidden);

    dim3 tb(32, 8);
    split_w1_kernel<<<dim3(2 * INTER / 32, HID / 32, NE), tb>>>(w_gu);
    split_w2_kernel<<<dim3(INTER / 32, HID / 32, NE), tb>>>(w_dn);

    // GEMM1: N tile covers 64 j (gate+up pair) -> grid.x = INTER/64
    gemm_split_kernel<HID, true><<<dim3(INTER / 64, CAP / 128, NE), 256, SMEM_BYTES>>>();
    // GEMM2: N tile covers 128 h cols -> grid.x = HID/128
    gemm_split_kernel<INTER, false><<<dim3(HID / 128, CAP / 128, NE), 256, SMEM_BYTES>>>();

    combine_kernel<<<T_TOK, 256>>>(aff, eidx, out);
}